// round 2
// baseline (speedup 1.0000x reference)
#include <cuda_runtime.h>
#include <math.h>

#define NB   2048
#define NDIM 128
#define MLZ  10
#define KAPPA 0.276f
#define TRI  8256      // 128*129/2
#define LPAD 8448      // padded packed triangular size (rows/cols padded to x4)

// smem layout (dynamic): Lr[8448] | Lc[8448] | vcur[128] | vprev[128] | yv[128] | tv[128] | U1s[128]
#define SMEM_FLOATS (2 * LPAD + 5 * NDIM)
#define SMEM_BYTES  (SMEM_FLOATS * 4)

__device__ float    g_scr[2 * NB];  // [0..NB) max|lam|^2, [NB..2NB) min|lam|^2
__device__ unsigned g_ctr = 0;

__device__ __forceinline__ float blockReduceSum(float v, float* red, int tid) {
    #pragma unroll
    for (int o = 16; o > 0; o >>= 1)
        v += __shfl_xor_sync(0xffffffffu, v, o);
    __syncthreads();
    if ((tid & 31) == 0) red[tid >> 5] = v;
    __syncthreads();
    return red[0] + red[1] + red[2] + red[3];
}

__device__ __forceinline__ int sturm_count(const float* a, const float* b2, float x) {
    float q = a[0] - x;
    int c = (q < 0.0f);
    #pragma unroll
    for (int i = 1; i < MLZ; i++) {
        float d = q;
        if (fabsf(d) < 1e-25f) d = (d < 0.0f) ? -1e-25f : 1e-25f;
        q = (a[i] - x) - b2[i - 1] / d;
        c += (q < 0.0f);
    }
    return c;
}

__global__ __launch_bounds__(128)
void spectrum_kernel(const float* __restrict__ net_out,
                     const float* __restrict__ U1,
                     const float* __restrict__ vin,
                     float* __restrict__ out) {
    extern __shared__ float sm[];
    float* Lr   = sm;                    // row-major packed, row i at rbase(i), len pad4(i+1)
    float* Lc   = sm + LPAD;             // col-major packed, col j at cbase(j), covers i in [4*(j>>2),128)
    float* vcur = sm + 2 * LPAD;
    float* vprev= vcur + NDIM;
    float* yv   = vprev + NDIM;
    float* tv   = yv + NDIM;
    float* U1s  = tv + NDIM;

    __shared__ float red[4];
    __shared__ float alph[MLZ], bet[MLZ], sc[4];
    __shared__ int   amLast;

    const int tid = threadIdx.x;
    const int b   = blockIdx.x;

    // ---- zero both L arrays (padding must be 0) ----
    {
        float4 z = make_float4(0.f, 0.f, 0.f, 0.f);
        float4* L4 = (float4*)Lr;                      // Lr & Lc contiguous
        #pragma unroll 4
        for (int idx = tid; idx < (2 * LPAD) / 4; idx += 128) L4[idx] = z;
    }
    U1s[tid] = U1[(size_t)b * NDIM + tid];
    float v0 = vin[(size_t)b * NDIM + tid];
    __syncthreads();

    // ---- build Lr and Lc from packed-tri gmem (coalesced float4 reads) ----
    {
        const float4* src4 = (const float4*)(net_out + (size_t)b * TRI);
        for (int idx = tid; idx < TRI / 4; idx += 128) {
            float4 v4 = src4[idx];
            int k = idx << 2;
            int i = (int)((__fsqrt_rn(8.0f * (float)k + 1.0f) - 1.0f) * 0.5f);
            while ((i + 1) * (i + 2) / 2 <= k) ++i;
            while (i * (i + 1) / 2 > k) --i;
            int j = k - i * (i + 1) / 2;
            float vals[4] = {v4.x, v4.y, v4.z, v4.w};
            #pragma unroll
            for (int m = 0; m < 4; m++) {
                int gi = i >> 2, ri = i & 3;
                int gj = j >> 2, rj = j & 3;
                Lr[4 * (gi + 1) * (2 * gi + ri) + j] = vals[m];
                Lc[(512 * gj - 8 * gj * (gj - 1) + rj * (128 - 4 * gj)) + i - 4 * gj] = vals[m];
                if (++j > i) { ++i; j = 0; }
            }
        }
    }

    // vn = v / ||v||  (reduce's barriers also publish the L builds)
    float nrm = sqrtf(blockReduceSum(v0 * v0, red, tid));
    vcur[tid]  = v0 / nrm;
    vprev[tid] = 0.0f;

    // ---- dd_opt stencil constants ----
    const int ii = tid >> 4, jj = (tid >> 1) & 7, cc = tid & 1;
    const int xip = (((ii + 1) & 7) << 4) | (jj << 1) | cc;
    const int xim = (((ii - 1) & 7) << 4) | (jj << 1) | cc;
    const int xjp = (ii << 4) | (((jj + 1) & 7) << 1) | cc;
    const int xjm = (ii << 4) | (((jj - 1) & 7) << 1) | cc;
    const float c_u0  = U1s[((ii << 3) + jj) << 1];
    const float c_u1  = U1s[(((ii << 3) + jj) << 1) + 1];
    const float c_u0m = U1s[((((ii - 1) & 7) << 3) + jj) << 1];
    const float c_u1m = U1s[(((ii << 3) + ((jj - 1) & 7)) << 1) + 1];

    // per-thread matvec bases (loop-invariant across the 10 steps)
    const int g   = tid >> 2;
    const int r   = tid & 3;
    const int rb4 = (g + 1) * (2 * g + r);             // row tid, float4 units
    const int cb4 = 128 * g - 2 * g * (g - 1) + r * (32 - g);  // col tid, float4 units
    const float4* Lr4 = (const float4*)Lr;
    const float4* Lc4 = (const float4*)Lc;
    const float4* yv4 = (const float4*)yv;
    const float4* tv4 = (const float4*)tv;

    float beta = 0.0f;
    __syncthreads();   // vcur visible

    for (int step = 0; step < MLZ; step++) {
        // y = D x (hop stencil)
        {
            float xc  = vcur[tid];
            float hop = c_u0  * vcur[xip] + c_u1  * vcur[xjp]
                      + c_u0m * vcur[xim] + c_u1m * vcur[xjm];
            yv[tid] = xc - KAPPA * hop;
        }
        __syncthreads();

        // t_j = sum_i L[i,j] y_i  — column j = tid, float4 over i-groups q=g..31
        {
            float acc = 0.0f;
            const float4* lp = Lc4 + cb4;
            #pragma unroll 4
            for (int q = g; q < 32; q++) {
                float4 l  = lp[q - g];
                float4 y4 = yv4[q];
                acc += l.x * y4.x + l.y * y4.y + l.z * y4.z + l.w * y4.w;
            }
            tv[tid] = acc;
        }
        __syncthreads();

        // w_i = sum_j L[i,j] t_j  — row i = tid, float4 over j-groups q=0..g
        float wacc = 0.0f;
        {
            const float4* lp = Lr4 + rb4;
            #pragma unroll 4
            for (int q = 0; q <= g; q++) {
                float4 l  = lp[q];
                float4 t4 = tv4[q];
                wacc += l.x * t4.x + l.y * t4.y + l.z * t4.z + l.w * t4.w;
            }
        }

        float al = blockReduceSum(wacc * vcur[tid], red, tid);
        float wn = wacc - al * vcur[tid] - beta * vprev[tid];
        float bn = sqrtf(blockReduceSum(wn * wn, red, tid));
        if (tid == 0) { alph[step] = al; bet[step] = bn; }
        vprev[tid] = vcur[tid];
        vcur[tid]  = wn / (bn + 1e-30f);
        beta = bn;
        __syncthreads();
    }

    // ---- 4 extremal/straddling eigenvalues via Sturm bisection ----
    if (tid < 4) {
        float a[MLZ], b2[MLZ - 1];
        #pragma unroll
        for (int i = 0; i < MLZ; i++) a[i] = alph[i];
        #pragma unroll
        for (int i = 0; i < MLZ - 1; i++) { float bb = bet[i]; b2[i] = bb * bb; }

        float lo = 3.0e38f, hi = -3.0e38f;
        #pragma unroll
        for (int i = 0; i < MLZ; i++) {
            float rad = 0.0f;
            if (i > 0)       rad += fabsf(bet[i - 1]);
            if (i < MLZ - 1) rad += fabsf(bet[i]);
            lo = fminf(lo, a[i] - rad);
            hi = fmaxf(hi, a[i] + rad);
        }

        int nneg = sturm_count(a, b2, 0.0f);
        int k;
        if      (tid == 0) k = 0;
        else if (tid == 1) k = MLZ - 1;
        else if (tid == 2) { k = nneg - 1; if (k < 0) k = 0; if (k > MLZ - 1) k = MLZ - 1; }
        else               { k = nneg;     if (k > MLZ - 1) k = MLZ - 1; }

        float l = lo, h = hi;
        #pragma unroll 1
        for (int it = 0; it < 44; it++) {
            float mid = 0.5f * (l + h);
            if (sturm_count(a, b2, mid) > k) h = mid; else l = mid;
        }
        sc[tid] = fabsf(0.5f * (l + h));
    }
    __syncthreads();
    if (tid == 0) {
        float mx = fmaxf(sc[0], sc[1]);
        float mn = fminf(sc[2], sc[3]);
        g_scr[b]      = mx * mx;
        g_scr[NB + b] = mn * mn;
        __threadfence();
        unsigned t = atomicAdd(&g_ctr, 1u);
        amLast = (t == NB - 1);
    }
    __syncthreads();

    // ---- last CTA reduces all batches (fixed order => deterministic) ----
    if (amLast) {
        __threadfence();
        const volatile float* scr = g_scr;
        float s1 = 0.0f, s2 = 0.0f;
        for (int i = tid; i < NB; i += 128) { s1 += scr[i]; s2 += scr[NB + i]; }
        float S1 = blockReduceSum(s1, red, tid);
        __syncthreads();
        float S2 = blockReduceSum(s2, red, tid);
        if (tid == 0) {
            out[0] = (S1 - S2) * (1.0f / (float)NB);
            g_ctr = 0;   // reset for next graph replay
        }
    }
}

extern "C" void kernel_launch(void* const* d_in, const int* in_sizes, int n_in,
                              void* d_out, int out_size) {
    const float* net_out = (const float*)d_in[0];
    const float* U1      = (const float*)d_in[1];
    const float* v       = (const float*)d_in[2];
    (void)in_sizes; (void)n_in; (void)out_size;

    static int attr_set = 0;
    if (!attr_set) {
        cudaFuncSetAttribute(spectrum_kernel,
                             cudaFuncAttributeMaxDynamicSharedMemorySize, SMEM_BYTES);
        attr_set = 1;
    }
    spectrum_kernel<<<NB, 128, SMEM_BYTES>>>(net_out, U1, v, (float*)d_out);
}

// round 3
// speedup vs baseline: 1.5444x; 1.5444x over previous
#include <cuda_runtime.h>
#include <math.h>

#define NB   2048
#define NDIM 128
#define MLZ  10
#define KAPPA 0.276f
#define TRI  8256      // 128*129/2
#define LPAD 8448      // packed tri, each row padded to multiple of 4 floats

// smem: Lp[8448] | vcur[128] | vprev[128] | yv[128] | tv[128] | U1s[128]
#define SMEM_FLOATS (LPAD + 5 * NDIM)
#define SMEM_BYTES  (SMEM_FLOATS * 4)

__device__ float    g_scr[2 * NB];   // [0..NB) max^2, [NB..2NB) min^2
__device__ unsigned g_ctr = 0;

__device__ __forceinline__ float blockReduceSum(float v, float* red, int tid) {
    #pragma unroll
    for (int o = 16; o > 0; o >>= 1)
        v += __shfl_xor_sync(0xffffffffu, v, o);
    __syncthreads();
    if ((tid & 31) == 0) red[tid >> 5] = v;
    __syncthreads();
    return red[0] + red[1] + red[2] + red[3];
}

__device__ __forceinline__ int sturm_count(const float* a, const float* b2, float x) {
    float q = a[0] - x;
    int c = (q < 0.0f);
    #pragma unroll
    for (int i = 1; i < MLZ; i++) {
        float d = q;
        if (fabsf(d) < 1e-25f) d = (d < 0.0f) ? -1e-25f : 1e-25f;
        q = (a[i] - x) - b2[i - 1] / d;
        c += (q < 0.0f);
    }
    return c;
}

__global__ __launch_bounds__(128)
void spectrum_kernel(const float* __restrict__ net_out,
                     const float* __restrict__ U1,
                     const float* __restrict__ vin,
                     float* __restrict__ out) {
    extern __shared__ float sm[];
    float* Lp    = sm;                 // padded packed: row i (g=i>>2, rm=i&3) at float4 idx (g+1)*(2g+rm), len (g+1) float4
    float* vcur  = sm + LPAD;
    float* vprev = vcur + NDIM;
    float* yv    = vprev + NDIM;
    float* tv    = yv + NDIM;
    float* U1s   = tv + NDIM;

    __shared__ float red[4];
    __shared__ float alph[MLZ], bet[MLZ], sc[4];
    __shared__ int   amLast;

    const int tid = threadIdx.x;
    const int b   = blockIdx.x;

    // ---- zero Lp (padding must be 0) ----
    {
        float4 z = make_float4(0.f, 0.f, 0.f, 0.f);
        float4* L4 = (float4*)Lp;
        #pragma unroll 4
        for (int i = tid; i < LPAD / 4; i += 128) L4[i] = z;
    }
    U1s[tid] = U1[(size_t)b * NDIM + tid];
    float v0 = vin[(size_t)b * NDIM + tid];
    __syncthreads();

    // ---- build padded packed Lp from gmem packed tri (coalesced float4 reads) ----
    {
        const float4* src4 = (const float4*)(net_out + (size_t)b * TRI);
        for (int idx = tid; idx < TRI / 4; idx += 128) {
            float4 v4 = src4[idx];
            int k = idx << 2;
            int i = (int)((__fsqrt_rn(8.0f * (float)k + 1.0f) - 1.0f) * 0.5f);
            while ((i + 1) * (i + 2) / 2 <= k) ++i;
            while (i * (i + 1) / 2 > k) --i;
            int j = k - i * (i + 1) / 2;
            float vals[4] = {v4.x, v4.y, v4.z, v4.w};
            #pragma unroll
            for (int m = 0; m < 4; m++) {
                int gi = i >> 2, ri = i & 3;
                Lp[4 * (gi + 1) * (2 * gi + ri) + j] = vals[m];
                if (++j > i) { ++i; j = 0; }
            }
        }
    }

    // vn = v / ||v||  (reduce barriers publish Lp/U1s too)
    float nrm = sqrtf(blockReduceSum(v0 * v0, red, tid));
    vcur[tid]  = v0 / nrm;
    vprev[tid] = 0.0f;

    // ---- dd_opt stencil constants ----
    const int ii = tid >> 4, jj = (tid >> 1) & 7, cc = tid & 1;
    const int xip = (((ii + 1) & 7) << 4) | (jj << 1) | cc;
    const int xim = (((ii - 1) & 7) << 4) | (jj << 1) | cc;
    const int xjp = (ii << 4) | (((jj + 1) & 7) << 1) | cc;
    const int xjm = (ii << 4) | (((jj - 1) & 7) << 1) | cc;
    const float c_u0  = U1s[((ii << 3) + jj) << 1];
    const float c_u1  = U1s[(((ii << 3) + jj) << 1) + 1];
    const float c_u0m = U1s[((((ii - 1) & 7) << 3) + jj) << 1];
    const float c_u1m = U1s[(((ii << 3) + ((jj - 1) & 7)) << 1) + 1];

    // loop-invariant matvec bases
    const int g    = tid >> 2;
    const int rb4  = (g + 1) * (2 * g + (tid & 3));   // this thread's row base, float4 units
    const int mb0  = (tid & ~31) >> 2;                // warp-uniform first i-group for column matvec
    const int cbase0 = 8 * (mb0 + 1) * mb0 + tid;     // 4*rb4(4*mb0) + j
    const float4* Lr4 = (const float4*)Lp;
    const float4* yv4 = (const float4*)yv;
    const float4* tv4 = (const float4*)tv;

    float beta = 0.0f;
    __syncthreads();   // vcur visible

    for (int step = 0; step < MLZ; step++) {
        // ---- y = D x (hop stencil) ----
        {
            float xc  = vcur[tid];
            float hop = c_u0  * vcur[xip] + c_u1  * vcur[xjp]
                      + c_u0m * vcur[xim] + c_u1m * vcur[xjm];
            yv[tid] = xc - KAPPA * hop;
        }
        __syncthreads();

        // ---- t_j = sum_{i>=j} L[i,j] y_i ----
        // warp-synchronized i; lane j = tid -> 32 consecutive floats per warp (conflict-free)
        {
            float a0 = 0.f, a1 = 0.f, a2 = 0.f, a3 = 0.f;
            int base = cbase0;          // float addr of L[i][j] for current i
            int len  = 4 * (mb0 + 1);   // current row length in floats
            for (int m = mb0; m < 32; m++) {
                float4 y4 = yv4[m];
                int i0 = m << 2;
                float l0 = Lp[base]; base += len;
                float l1 = Lp[base]; base += len;
                float l2 = Lp[base]; base += len;
                float l3 = Lp[base]; base += len;
                if (i0     >= tid) a0 += l0 * y4.x;
                if (i0 + 1 >= tid) a1 += l1 * y4.y;
                if (i0 + 2 >= tid) a2 += l2 * y4.z;
                if (i0 + 3 >= tid) a3 += l3 * y4.w;
                len += 4;
            }
            tv[tid] = (a0 + a1) + (a2 + a3);
        }
        __syncthreads();

        // ---- w_i = sum_{j<=i} L[i,j] t_j ----
        // thread = row, float4 self loads, uniform float4 broadcast of t
        float wacc;
        {
            float ax = 0.f, ay = 0.f, az = 0.f, aw = 0.f;
            #pragma unroll 4
            for (int q = 0; q <= g; q++) {
                float4 l  = Lr4[rb4 + q];
                float4 t4 = tv4[q];
                ax += l.x * t4.x; ay += l.y * t4.y;
                az += l.z * t4.z; aw += l.w * t4.w;
            }
            wacc = (ax + ay) + (az + aw);
        }

        // ---- Lanczos recurrence ----
        float al = blockReduceSum(wacc * vcur[tid], red, tid);
        float wn = wacc - al * vcur[tid] - beta * vprev[tid];
        float bn = sqrtf(blockReduceSum(wn * wn, red, tid));
        if (tid == 0) { alph[step] = al; bet[step] = bn; }
        vprev[tid] = vcur[tid];
        vcur[tid]  = wn / (bn + 1e-30f);
        beta = bn;
        __syncthreads();
    }

    // ---- 4 needed eigenvalues via Sturm bisection ----
    if (tid < 4) {
        float a[MLZ], b2[MLZ - 1];
        #pragma unroll
        for (int i = 0; i < MLZ; i++) a[i] = alph[i];
        #pragma unroll
        for (int i = 0; i < MLZ - 1; i++) { float bb = bet[i]; b2[i] = bb * bb; }

        float lo = 3.0e38f, hi = -3.0e38f;
        #pragma unroll
        for (int i = 0; i < MLZ; i++) {
            float rad = 0.0f;
            if (i > 0)       rad += fabsf(bet[i - 1]);
            if (i < MLZ - 1) rad += fabsf(bet[i]);
            lo = fminf(lo, a[i] - rad);
            hi = fmaxf(hi, a[i] + rad);
        }

        int nneg = sturm_count(a, b2, 0.0f);
        int k;
        if      (tid == 0) k = 0;
        else if (tid == 1) k = MLZ - 1;
        else if (tid == 2) { k = nneg - 1; if (k < 0) k = 0; if (k > MLZ - 1) k = MLZ - 1; }
        else               { k = nneg;     if (k > MLZ - 1) k = MLZ - 1; }

        float l = lo, h = hi;
        #pragma unroll 1
        for (int it = 0; it < 44; it++) {
            float mid = 0.5f * (l + h);
            if (sturm_count(a, b2, mid) > k) h = mid; else l = mid;
        }
        sc[tid] = fabsf(0.5f * (l + h));
    }
    __syncthreads();
    if (tid == 0) {
        float mx = fmaxf(sc[0], sc[1]);
        float mn = fminf(sc[2], sc[3]);
        g_scr[b]      = mx * mx;
        g_scr[NB + b] = mn * mn;
        __threadfence();
        unsigned t = atomicAdd(&g_ctr, 1u);
        amLast = (t == NB - 1);
    }
    __syncthreads();

    // ---- last CTA reduces all batches (fixed order => deterministic) ----
    if (amLast) {
        __threadfence();
        const volatile float* scr = g_scr;
        float s1 = 0.0f, s2 = 0.0f;
        for (int i = tid; i < NB; i += 128) { s1 += scr[i]; s2 += scr[NB + i]; }
        float S1 = blockReduceSum(s1, red, tid);
        __syncthreads();
        float S2 = blockReduceSum(s2, red, tid);
        if (tid == 0) {
            out[0] = (S1 - S2) * (1.0f / (float)NB);
            g_ctr = 0;   // reset for next graph replay
        }
    }
}

extern "C" void kernel_launch(void* const* d_in, const int* in_sizes, int n_in,
                              void* d_out, int out_size) {
    const float* net_out = (const float*)d_in[0];
    const float* U1      = (const float*)d_in[1];
    const float* v       = (const float*)d_in[2];
    (void)in_sizes; (void)n_in; (void)out_size;

    spectrum_kernel<<<NB, 128, SMEM_BYTES>>>(net_out, U1, v, (float*)d_out);
}